// round 7
// baseline (speedup 1.0000x reference)
#include <cuda_runtime.h>
#include <cuda_bf16.h>
#include <math.h>
#include <stdint.h>

// Problem constants (reference: G=2048, CROPS=4, D=128 -> N=8192)
#define N_ROWS 8192
#define DIM    128
#define NP     (N_ROWS / 128)            // 64 row panels
#define LSTRIP 8                         // J-tiles per CTA strip

#define EXP2_SCALE 2.8853900817779268f   // 1/(tau*ln2), tau=0.5
#define SQRT_E2S   1.6986436f            // sqrt(EXP2_SCALE), folded into bf16 z
#define EXP_SELF   7.38905609893065f     // exp(1/tau) = e^2

// Scratch (device globals; no allocation anywhere)
__device__ float          g_z[N_ROWS * DIM];        // fp32 normalized (unscaled)
__device__ __nv_bfloat16  g_zb[N_ROWS * DIM];       // bf16 normalized * sqrt(scale)
__device__ float          g_P[NP * NP * 128];       // per-(panel,slot) partial sums
__device__ float          g_part[N_ROWS / 8];       // per-CTA partial losses
__device__ int            g_sync;                   // last-CTA counter (self-resetting)

// ---------------------------------------------------------------------------
// helpers
// ---------------------------------------------------------------------------
static __device__ __forceinline__ uint32_t smem_u32(const void* p) {
    uint32_t a;
    asm("{ .reg .u64 t; cvta.to.shared.u64 t, %1; cvt.u32.u64 %0, t; }"
        : "=r"(a) : "l"(p));
    return a;
}

#define LDSM_X4(r0, r1, r2, r3, addr)                                          \
    asm volatile("ldmatrix.sync.aligned.m8n8.x4.shared.b16 {%0,%1,%2,%3}, [%4];" \
                 : "=r"(r0), "=r"(r1), "=r"(r2), "=r"(r3) : "r"(addr))

#define MMA16816(d, a, b0, b1)                                                 \
    asm volatile("mma.sync.aligned.m16n8k16.row.col.f32.bf16.bf16.f32 "        \
                 "{%0,%1,%2,%3},{%4,%5,%6,%7},{%8,%9},{%0,%1,%2,%3};"          \
                 : "+f"((d)[0]), "+f"((d)[1]), "+f"((d)[2]), "+f"((d)[3])      \
                 : "r"((a)[0]), "r"((a)[1]), "r"((a)[2]), "r"((a)[3]),         \
                   "r"(b0), "r"(b1))

#define CP_ASYNC16(dst, src)                                                   \
    asm volatile("cp.async.cg.shared.global [%0], [%1], 16;"                   \
                 :: "r"(dst), "l"(src) : "memory")
#define CP_COMMIT() asm volatile("cp.async.commit_group;" ::: "memory")
#define CP_WAIT(N)  asm volatile("cp.async.wait_group %0;" :: "n"(N) : "memory")

static __device__ __forceinline__ float ex2_fast(float x) {
    float y;
    asm("ex2.approx.ftz.f32 %0, %1;" : "=f"(y) : "f"(x));
    return y;
}

// Swizzled tile layout (128 rows x 16 chunks of 16B, conflict-free ldmatrix):
// off(r,c) = (c>>3)*16384 + r*128 + ((c&7)^(r&7))*16
static __device__ __forceinline__ uint32_t tile_off(int r, int c) {
    return ((uint32_t)(c >> 3) << 14) + ((uint32_t)r << 7)
         + ((uint32_t)((c & 7) ^ (r & 7)) << 4);
}

// async-copy one 128x128 bf16 panel (rows r0..r0+127) into swizzled smem
static __device__ __forceinline__ void cp_tile(uint32_t dst, int r0, int tid) {
    const char* src = (const char*)g_zb + (size_t)r0 * 256;
    #pragma unroll
    for (int it = 0; it < 8; it++) {
        int idx = tid + it * 256;       // 2048 chunks of 16B
        int r = idx >> 4;
        int c = idx & 15;
        CP_ASYNC16(dst + tile_off(r, c), src + (size_t)r * 256 + c * 16);
    }
}

// ---------------------------------------------------------------------------
// Kernel A: row-normalize; fp32 copy + bf16 copy pre-scaled by sqrt(EXP2_SCALE)
// ---------------------------------------------------------------------------
__global__ void k_normalize(const float* __restrict__ f, int n) {
    int warp = (blockIdx.x * blockDim.x + threadIdx.x) >> 5;
    int lane = threadIdx.x & 31;
    if (warp >= n) return;
    const float* row = f + (size_t)warp * DIM;
    float v0 = row[lane], v1 = row[lane + 32], v2 = row[lane + 64], v3 = row[lane + 96];
    float ss = v0 * v0 + v1 * v1 + v2 * v2 + v3 * v3;
    #pragma unroll
    for (int o = 16; o; o >>= 1) ss += __shfl_xor_sync(0xffffffffu, ss, o);
    float inv = 1.0f / fmaxf(sqrtf(ss), 1e-8f);
    float z0 = v0 * inv, z1 = v1 * inv, z2 = v2 * inv, z3 = v3 * inv;
    float* z = g_z + (size_t)warp * DIM;
    z[lane] = z0; z[lane + 32] = z1; z[lane + 64] = z2; z[lane + 96] = z3;
    __nv_bfloat16* zb = g_zb + (size_t)warp * DIM;
    zb[lane]      = __float2bfloat16(z0 * SQRT_E2S);
    zb[lane + 32] = __float2bfloat16(z1 * SQRT_E2S);
    zb[lane + 64] = __float2bfloat16(z2 * SQRT_E2S);
    zb[lane + 96] = __float2bfloat16(z3 * SQRT_E2S);
}

// ---------------------------------------------------------------------------
// Kernel B: symmetric-strip HMMA, occ 2. CTA = tiles (I, J0..J0+nt-1) with
// A panel loaded once and B panels double-buffered (prefetch t+2 while
// computing t). Mainloop per tile = round-6 nbb-interleaved MMA/ex2 body.
// Per-tile parity reduction slots; two cheap barriers per tile, zero cold
// memory waits after the strip prologue.
// ---------------------------------------------------------------------------
__global__ void __launch_bounds__(256, 2)
k_scores_strip() {
    const int I  = blockIdx.x;
    const int J0 = I + blockIdx.y * LSTRIP;
    if (J0 >= NP) return;
    const int nt = (NP - J0 < LSTRIP) ? (NP - J0) : LSTRIP;

    extern __shared__ __align__(1024) char smem[];
    __shared__ float red[2][128][2];      // row sums:  [parity][row][warpN]
    __shared__ float colred[2][128][4];   // col sums:  [parity][col][warpM]

    const uint32_t Abase = smem_u32(smem);
    const uint32_t Bbase[2] = { Abase + 32768u, Abase + 65536u };

    const int tid   = threadIdx.x;
    const int lane  = tid & 31;
    const int w     = tid >> 5;
    const int warpM = w & 3;
    const int warpN = w >> 2;

    // Strip prologue: A + B0 (group0); B1 (group1); wait for group0.
    cp_tile(Abase, I * 128, tid);
    cp_tile(Bbase[0], J0 * 128, tid);
    CP_COMMIT();
    if (nt > 1) cp_tile(Bbase[1], (J0 + 1) * 128, tid);
    CP_COMMIT();
    CP_WAIT(1);
    __syncthreads();

    const int aRow = warpM * 32 + (lane & 15);
    const int aSel = lane >> 4;
    const int bRow = (lane & 7) + ((lane >> 4) & 1) * 8;
    const int bSel = (lane >> 3) & 1;

    for (int t = 0; t < nt; t++) {
        const int buf = t & 1;
        const uint32_t Bb = Bbase[buf];

        float rs[2][2] = {{0.f, 0.f}, {0.f, 0.f}};

        #pragma unroll
        for (int nbb = 0; nbb < 2; nbb++) {       // n-half-block: cols nbb*32..+31
            float acc[2][2][2][4];                 // [mb][nb2loc][sub][q]
            #pragma unroll
            for (int mb = 0; mb < 2; mb++)
                #pragma unroll
                for (int u = 0; u < 2; u++)
                    #pragma unroll
                    for (int v = 0; v < 2; v++)
                        #pragma unroll
                        for (int q = 0; q < 4; q++) acc[mb][u][v][q] = 0.0f;

            #pragma unroll
            for (int ks = 0; ks < 8; ks++) {
                uint32_t af[2][4];
                #pragma unroll
                for (int mb = 0; mb < 2; mb++)
                    LDSM_X4(af[mb][0], af[mb][1], af[mb][2], af[mb][3],
                            Abase + tile_off(aRow + mb * 16, ks * 2 + aSel));
                #pragma unroll
                for (int u = 0; u < 2; u++) {
                    uint32_t b0, b1, b2, b3;
                    LDSM_X4(b0, b1, b2, b3,
                            Bb + tile_off(warpN * 64 + (nbb * 2 + u) * 16 + bRow,
                                          ks * 2 + bSel));
                    #pragma unroll
                    for (int mb = 0; mb < 2; mb++) {
                        MMA16816(acc[mb][u][0], af[mb], b0, b1);
                        MMA16816(acc[mb][u][1], af[mb], b2, b3);
                    }
                }
            }

            // Block epilogue: ex2 + partial sums (overlaps next block's MMAs)
            float cs[8];
            #pragma unroll
            for (int k = 0; k < 8; k++) cs[k] = 0.f;

            #pragma unroll
            for (int mb = 0; mb < 2; mb++)
                #pragma unroll
                for (int u = 0; u < 2; u++)
                    #pragma unroll
                    for (int v = 0; v < 2; v++)
                        #pragma unroll
                        for (int q = 0; q < 4; q++) {
                            float e = ex2_fast(acc[mb][u][v][q]);
                            rs[mb][q >> 1]                += e;
                            cs[(u * 2 + v) * 2 + (q & 1)] += e;
                        }

            #pragma unroll
            for (int k = 0; k < 8; k++) {
                cs[k] += __shfl_xor_sync(0xffffffffu, cs[k], 4);
                cs[k] += __shfl_xor_sync(0xffffffffu, cs[k], 8);
                cs[k] += __shfl_xor_sync(0xffffffffu, cs[k], 16);
            }
            if (lane < 4) {
                #pragma unroll
                for (int k = 0; k < 8; k++) {
                    int nb = nbb * 4 + (k >> 1);
                    colred[buf][warpN * 64 + nb * 8 + lane * 2 + (k & 1)][warpM] = cs[k];
                }
            }
        }

        #pragma unroll
        for (int mb = 0; mb < 2; mb++)
            #pragma unroll
            for (int h = 0; h < 2; h++) {
                rs[mb][h] += __shfl_xor_sync(0xffffffffu, rs[mb][h], 1);
                rs[mb][h] += __shfl_xor_sync(0xffffffffu, rs[mb][h], 2);
            }
        if ((lane & 3) == 0) {
            int gq = lane >> 2;
            #pragma unroll
            for (int mb = 0; mb < 2; mb++)
                #pragma unroll
                for (int h = 0; h < 2; h++)
                    red[buf][warpM * 32 + mb * 16 + h * 8 + gq][warpN] = rs[mb][h];
        }

        __syncthreads();   // tile t slots complete; B[buf] reads complete

        // Prefetch B(t+2) into the buffer tile t just finished reading
        if (t + 2 < nt) {
            cp_tile(Bbase[buf], (J0 + t + 2) * 128, tid);
            CP_COMMIT();
            CP_WAIT(1);    // B(t+1) resident
        } else {
            CP_WAIT(0);
        }

        // Gather + store g_P for tile t
        if (tid < 128) {
            const int J = J0 + t;
            float r = red[buf][tid][0] + red[buf][tid][1];
            g_P[((size_t)I * NP + J) * 128 + tid] = r;
            if (J != I) {
                float c = colred[buf][tid][0] + colred[buf][tid][1]
                        + colred[buf][tid][2] + colred[buf][tid][3];
                g_P[((size_t)J * NP + I) * 128 + tid] = c;
            }
        }
        __syncthreads();   // B(t+1) visible to all; slot[buf] free for t+2
    }
}

// ---------------------------------------------------------------------------
// Kernel C: gather S + fp32 pos + per-row loss + CTA partials + fused final
// reduction (deterministic last-CTA pattern; counter self-resets per replay)
// ---------------------------------------------------------------------------
__global__ void k_rowloss(float* __restrict__ out, int n, int cr) {
    __shared__ float tvals[8];
    __shared__ int   s_last;
    __shared__ float sm[256];

    int row  = blockIdx.x * 8 + (threadIdx.x >> 5);
    int lane = threadIdx.x & 31;
    float tv = 0.0f;
    if (row < n) {
        const float* zr = g_z + (size_t)row * DIM;
        float a0 = zr[lane], a1 = zr[lane + 32], a2 = zr[lane + 64], a3 = zr[lane + 96];
        int gb = (row / cr) * cr;
        float P = 0.0f;
        for (int jj = 0; jj < cr; jj++) {
            const float* zc = g_z + (size_t)(gb + jj) * DIM;
            float d = a0 * zc[lane] + a1 * zc[lane + 32] + a2 * zc[lane + 64] + a3 * zc[lane + 96];
            #pragma unroll
            for (int o = 16; o; o >>= 1) d += __shfl_xor_sync(0xffffffffu, d, o);
            P += exp2f(d * EXP2_SCALE);
        }
        int Ip   = row >> 7;
        int r127 = row & 127;
        const float* pbase = g_P + (size_t)Ip * NP * 128 + r127;
        float s = pbase[(size_t)lane * 128] + pbase[(size_t)(lane + 32) * 128];
        #pragma unroll
        for (int o = 16; o; o >>= 1) s += __shfl_xor_sync(0xffffffffu, s, o);

        float pos = P - EXP_SELF;
        float neg = s - P;
        tv = logf(neg) - logf(pos);
    }
    if (lane == 0) tvals[threadIdx.x >> 5] = tv;
    __syncthreads();
    if (threadIdx.x == 0) {
        float acc = 0.0f;
        #pragma unroll
        for (int u = 0; u < 8; u++) acc += tvals[u];
        g_part[blockIdx.x] = acc;
        __threadfence();
        int old = atomicAdd(&g_sync, 1);
        s_last = (old == (int)gridDim.x - 1);
    }
    __syncthreads();

    if (s_last) {
        if (threadIdx.x == 0) g_sync = 0;   // reset for next graph replay
        __threadfence();
        int t = threadIdx.x;
        int m = gridDim.x;
        float s = 0.0f;
        for (int idx = t; idx < m; idx += 256)
            s += __ldcg(&g_part[idx]);      // fixed-order, L2 loads
        sm[t] = s;
        __syncthreads();
        #pragma unroll
        for (int off = 128; off; off >>= 1) {
            if (t < off) sm[t] += sm[t + off];
            __syncthreads();
        }
        if (t == 0) out[0] = sm[0] / (float)n;
    }
}

// ---------------------------------------------------------------------------
extern "C" void kernel_launch(void* const* d_in, const int* in_sizes, int n_in,
                              void* d_out, int out_size) {
    const float* features = (const float*)d_in[0];
    int n  = in_sizes[0] / DIM;   // 8192
    int g  = in_sizes[1];         // 2048
    int cr = n / g;               // 4

    const int SMEM_DYN = 3 * 32768;   // A + B0 + B1
    cudaFuncSetAttribute(k_scores_strip,
                         cudaFuncAttributeMaxDynamicSharedMemorySize, SMEM_DYN);

    k_normalize<<<n / 8, 256>>>(features, n);
    dim3 grid_b(NP, (NP + LSTRIP - 1) / LSTRIP);
    k_scores_strip<<<grid_b, 256, SMEM_DYN>>>();
    k_rowloss<<<n / 8, 256>>>((float*)d_out, n, cr);
}

// round 8
// speedup vs baseline: 1.0433x; 1.0433x over previous
#include <cuda_runtime.h>
#include <cuda_bf16.h>
#include <math.h>
#include <stdint.h>

// Problem constants (reference: G=2048, CROPS=4, D=128 -> N=8192)
#define N_ROWS 8192
#define DIM    128
#define NP     (N_ROWS / 128)            // 64 row panels
#define NTRI   (NP * (NP + 1) / 2)       // 2080 upper-triangle tiles

#define EXP2_SCALE 2.8853900817779268f   // 1/(tau*ln2), tau=0.5
#define SQRT_E2S   1.6986436f            // sqrt(EXP2_SCALE), folded into bf16 z
#define EXP_SELF   7.38905609893065f     // exp(1/tau) = e^2

// Scratch (device globals; no allocation anywhere)
__device__ float          g_z[N_ROWS * DIM];        // fp32 normalized (unscaled)
__device__ __nv_bfloat16  g_zb[N_ROWS * DIM];       // bf16 normalized * sqrt(scale)
__device__ float          g_P[NP * NP * 128];       // per-(panel,slot) partial sums
__device__ float          g_part[N_ROWS / 8];       // per-CTA partial losses
__device__ int            g_sync;                   // last-CTA counter (self-resetting)

// ---------------------------------------------------------------------------
// helpers
// ---------------------------------------------------------------------------
static __device__ __forceinline__ uint32_t smem_u32(const void* p) {
    uint32_t a;
    asm("{ .reg .u64 t; cvta.to.shared.u64 t, %1; cvt.u32.u64 %0, t; }"
        : "=r"(a) : "l"(p));
    return a;
}

#define LDSM_X4(r0, r1, r2, r3, addr)                                          \
    asm volatile("ldmatrix.sync.aligned.m8n8.x4.shared.b16 {%0,%1,%2,%3}, [%4];" \
                 : "=r"(r0), "=r"(r1), "=r"(r2), "=r"(r3) : "r"(addr))

#define MMA16816(d, a, b0, b1)                                                 \
    asm volatile("mma.sync.aligned.m16n8k16.row.col.f32.bf16.bf16.f32 "        \
                 "{%0,%1,%2,%3},{%4,%5,%6,%7},{%8,%9},{%0,%1,%2,%3};"          \
                 : "+f"((d)[0]), "+f"((d)[1]), "+f"((d)[2]), "+f"((d)[3])      \
                 : "r"((a)[0]), "r"((a)[1]), "r"((a)[2]), "r"((a)[3]),         \
                   "r"(b0), "r"(b1))

#define CP_ASYNC16(dst, src)                                                   \
    asm volatile("cp.async.cg.shared.global [%0], [%1], 16;"                   \
                 :: "r"(dst), "l"(src) : "memory")
#define CP_COMMIT() asm volatile("cp.async.commit_group;" ::: "memory")
#define CP_WAIT(N)  asm volatile("cp.async.wait_group %0;" :: "n"(N) : "memory")

static __device__ __forceinline__ float ex2_fast(float x) {
    float y;
    asm("ex2.approx.ftz.f32 %0, %1;" : "=f"(y) : "f"(x));
    return y;
}

// Swizzled tile layout (128 rows x 16 chunks of 16B, conflict-free ldmatrix):
// off(r,c) = (c>>3)*16384 + r*128 + ((c&7)^(r&7))*16
static __device__ __forceinline__ uint32_t tile_off(int r, int c) {
    return ((uint32_t)(c >> 3) << 14) + ((uint32_t)r << 7)
         + ((uint32_t)((c & 7) ^ (r & 7)) << 4);
}

// async-copy one 128x128 bf16 panel (rows r0..r0+127) into swizzled smem
static __device__ __forceinline__ void cp_tile(uint32_t dst, int r0, int tid) {
    const char* src = (const char*)g_zb + (size_t)r0 * 256;
    #pragma unroll
    for (int it = 0; it < 8; it++) {
        int idx = tid + it * 256;       // 2048 chunks of 16B
        int r = idx >> 4;
        int c = idx & 15;
        CP_ASYNC16(dst + tile_off(r, c), src + (size_t)r * 256 + c * 16);
    }
}

// ---------------------------------------------------------------------------
// Kernel A: row-normalize; fp32 copy + bf16 copy pre-scaled by sqrt(EXP2_SCALE)
// ---------------------------------------------------------------------------
__global__ void k_normalize(const float* __restrict__ f, int n) {
    int warp = (blockIdx.x * blockDim.x + threadIdx.x) >> 5;
    int lane = threadIdx.x & 31;
    if (warp >= n) return;
    const float* row = f + (size_t)warp * DIM;
    float v0 = row[lane], v1 = row[lane + 32], v2 = row[lane + 64], v3 = row[lane + 96];
    float ss = v0 * v0 + v1 * v1 + v2 * v2 + v3 * v3;
    #pragma unroll
    for (int o = 16; o; o >>= 1) ss += __shfl_xor_sync(0xffffffffu, ss, o);
    float inv = 1.0f / fmaxf(sqrtf(ss), 1e-8f);
    float z0 = v0 * inv, z1 = v1 * inv, z2 = v2 * inv, z3 = v3 * inv;
    float* z = g_z + (size_t)warp * DIM;
    z[lane] = z0; z[lane + 32] = z1; z[lane + 64] = z2; z[lane + 96] = z3;
    __nv_bfloat16* zb = g_zb + (size_t)warp * DIM;
    zb[lane]      = __float2bfloat16(z0 * SQRT_E2S);
    zb[lane + 32] = __float2bfloat16(z1 * SQRT_E2S);
    zb[lane + 64] = __float2bfloat16(z2 * SQRT_E2S);
    zb[lane + 96] = __float2bfloat16(z3 * SQRT_E2S);
}

// ---------------------------------------------------------------------------
// Kernel B: symmetric-tile HMMA, one 128x128 tile per CTA, 1D triangular grid.
// A fragments loaded ONCE per CTA straight from gmem into 64 persistent regs
// (no smem for A); B panel via cp.async + ldmatrix (minimal 16KB/warp reads).
// Mainloop = nbb-interleaved MMA/ex2 (round-6 winning body). occ 2.
// ---------------------------------------------------------------------------
__global__ void __launch_bounds__(256, 2)
k_scores_sym() {
    // map linear bid -> upper-triangle (I, J)
    int bid = blockIdx.x;
    int I;
    {
        float disc = sqrtf((float)(129 * 129 - 8 * bid));
        I = (int)((129.0f - disc) * 0.5f);
        if (I > 63) I = 63;
        if (I < 0) I = 0;
        while (I * NP - (I * (I - 1)) / 2 > bid) I--;
        while ((I + 1) * NP - ((I + 1) * I) / 2 <= bid) I++;
    }
    const int J = I + (bid - (I * NP - (I * (I - 1)) / 2));

    extern __shared__ __align__(1024) char smem[];
    __shared__ float red[128][2];      // row sums: [row][warpN]
    __shared__ float colred[128][4];   // col sums: [col][warpM]

    const uint32_t Bbase = smem_u32(smem);

    const int tid   = threadIdx.x;
    const int lane  = tid & 31;
    const int w     = tid >> 5;
    const int warpM = w & 3;
    const int warpN = w >> 2;

    // B panel via cp.async (32KB)
    cp_tile(Bbase, J * 128, tid);
    CP_COMMIT();

    // A fragments via direct LDG (persistent, 64 regs). m16n8k16 A layout:
    // lane L: g=L>>2, c2=(L&3)*2; regs = A[g][c2], A[g+8][c2], A[g][c2+8], A[g+8][c2+8]
    uint32_t afrag[2][8][4];
    {
        const char* Ag = (const char*)g_zb
                       + (size_t)(I * 128 + warpM * 32) * 256;   // 256B per row
        const int g  = lane >> 2;
        const int c2 = (lane & 3) * 2;
        #pragma unroll
        for (int mb = 0; mb < 2; mb++)
            #pragma unroll
            for (int ks = 0; ks < 8; ks++) {
                const char* base = Ag + (size_t)(mb * 16 + g) * 256
                                 + (ks * 16 + c2) * 2;
                afrag[mb][ks][0] = __ldg((const uint32_t*)(base));
                afrag[mb][ks][1] = __ldg((const uint32_t*)(base + 8 * 256));
                afrag[mb][ks][2] = __ldg((const uint32_t*)(base + 16));
                afrag[mb][ks][3] = __ldg((const uint32_t*)(base + 8 * 256 + 16));
            }
    }

    CP_WAIT(0);
    __syncthreads();

    const int bRow = (lane & 7) + ((lane >> 4) & 1) * 8;
    const int bSel = (lane >> 3) & 1;

    float rs[2][2] = {{0.f, 0.f}, {0.f, 0.f}};

    #pragma unroll
    for (int nbb = 0; nbb < 2; nbb++) {       // n-half-block: cols nbb*32..+31
        float acc[2][2][2][4];                 // [mb][nb2loc][sub][q]
        #pragma unroll
        for (int mb = 0; mb < 2; mb++)
            #pragma unroll
            for (int u = 0; u < 2; u++)
                #pragma unroll
                for (int v = 0; v < 2; v++)
                    #pragma unroll
                    for (int q = 0; q < 4; q++) acc[mb][u][v][q] = 0.0f;

        #pragma unroll
        for (int ks = 0; ks < 8; ks++) {
            #pragma unroll
            for (int u = 0; u < 2; u++) {
                uint32_t b0, b1, b2, b3;
                LDSM_X4(b0, b1, b2, b3,
                        Bbase + tile_off(warpN * 64 + (nbb * 2 + u) * 16 + bRow,
                                         ks * 2 + bSel));
                #pragma unroll
                for (int mb = 0; mb < 2; mb++) {
                    MMA16816(acc[mb][u][0], afrag[mb][ks], b0, b1);
                    MMA16816(acc[mb][u][1], afrag[mb][ks], b2, b3);
                }
            }
        }

        // Block epilogue: ex2 + partial sums (overlaps next block's MMAs)
        float cs[8];
        #pragma unroll
        for (int k = 0; k < 8; k++) cs[k] = 0.f;

        #pragma unroll
        for (int mb = 0; mb < 2; mb++)
            #pragma unroll
            for (int u = 0; u < 2; u++)
                #pragma unroll
                for (int v = 0; v < 2; v++)
                    #pragma unroll
                    for (int q = 0; q < 4; q++) {
                        float e = ex2_fast(acc[mb][u][v][q]);
                        rs[mb][q >> 1]                += e;
                        cs[(u * 2 + v) * 2 + (q & 1)] += e;
                    }

        // col reduce across lane>>2 (rows); lane<4 then holds col groups
        #pragma unroll
        for (int k = 0; k < 8; k++) {
            cs[k] += __shfl_xor_sync(0xffffffffu, cs[k], 4);
            cs[k] += __shfl_xor_sync(0xffffffffu, cs[k], 8);
            cs[k] += __shfl_xor_sync(0xffffffffu, cs[k], 16);
        }
        if (lane < 4) {
            #pragma unroll
            for (int k = 0; k < 8; k++) {
                int nb = nbb * 4 + (k >> 1);           // global 8-col group
                colred[warpN * 64 + nb * 8 + lane * 2 + (k & 1)][warpM] = cs[k];
            }
        }
    }

    // row reduce across lane&3 (cols)
    #pragma unroll
    for (int mb = 0; mb < 2; mb++)
        #pragma unroll
        for (int h = 0; h < 2; h++) {
            rs[mb][h] += __shfl_xor_sync(0xffffffffu, rs[mb][h], 1);
            rs[mb][h] += __shfl_xor_sync(0xffffffffu, rs[mb][h], 2);
        }
    if ((lane & 3) == 0) {
        int gq = lane >> 2;
        #pragma unroll
        for (int mb = 0; mb < 2; mb++)
            #pragma unroll
            for (int h = 0; h < 2; h++)
                red[warpM * 32 + mb * 16 + h * 8 + gq][warpN] = rs[mb][h];
    }
    __syncthreads();

    if (tid < 128) {
        float r = red[tid][0] + red[tid][1];
        g_P[((size_t)I * NP + J) * 128 + tid] = r;
        if (I != J) {
            float c = colred[tid][0] + colred[tid][1]
                    + colred[tid][2] + colred[tid][3];
            g_P[((size_t)J * NP + I) * 128 + tid] = c;
        }
    }
}

// ---------------------------------------------------------------------------
// Kernel C: gather S + fp32 pos + per-row loss + CTA partials + fused final
// reduction (deterministic last-CTA pattern; counter self-resets per replay)
// ---------------------------------------------------------------------------
__global__ void k_rowloss(float* __restrict__ out, int n, int cr) {
    __shared__ float tvals[8];
    __shared__ int   s_last;
    __shared__ float sm[256];

    int row  = blockIdx.x * 8 + (threadIdx.x >> 5);
    int lane = threadIdx.x & 31;
    float tv = 0.0f;
    if (row < n) {
        const float* zr = g_z + (size_t)row * DIM;
        float a0 = zr[lane], a1 = zr[lane + 32], a2 = zr[lane + 64], a3 = zr[lane + 96];
        int gb = (row / cr) * cr;
        float P = 0.0f;
        for (int jj = 0; jj < cr; jj++) {
            const float* zc = g_z + (size_t)(gb + jj) * DIM;
            float d = a0 * zc[lane] + a1 * zc[lane + 32] + a2 * zc[lane + 64] + a3 * zc[lane + 96];
            #pragma unroll
            for (int o = 16; o; o >>= 1) d += __shfl_xor_sync(0xffffffffu, d, o);
            P += exp2f(d * EXP2_SCALE);
        }
        int Ip   = row >> 7;
        int r127 = row & 127;
        const float* pbase = g_P + (size_t)Ip * NP * 128 + r127;
        float s = pbase[(size_t)lane * 128] + pbase[(size_t)(lane + 32) * 128];
        #pragma unroll
        for (int o = 16; o; o >>= 1) s += __shfl_xor_sync(0xffffffffu, s, o);

        float pos = P - EXP_SELF;
        float neg = s - P;
        tv = logf(neg) - logf(pos);
    }
    if (lane == 0) tvals[threadIdx.x >> 5] = tv;
    __syncthreads();
    if (threadIdx.x == 0) {
        float acc = 0.0f;
        #pragma unroll
        for (int u = 0; u < 8; u++) acc += tvals[u];
        g_part[blockIdx.x] = acc;
        __threadfence();
        int old = atomicAdd(&g_sync, 1);
        s_last = (old == (int)gridDim.x - 1);
    }
    __syncthreads();

    if (s_last) {
        if (threadIdx.x == 0) g_sync = 0;   // reset for next graph replay
        __threadfence();
        int t = threadIdx.x;
        int m = gridDim.x;
        float s = 0.0f;
        for (int idx = t; idx < m; idx += 256)
            s += __ldcg(&g_part[idx]);      // fixed-order, L2 loads
        sm[t] = s;
        __syncthreads();
        #pragma unroll
        for (int off = 128; off; off >>= 1) {
            if (t < off) sm[t] += sm[t + off];
            __syncthreads();
        }
        if (t == 0) out[0] = sm[0] / (float)n;
    }
}

// ---------------------------------------------------------------------------
extern "C" void kernel_launch(void* const* d_in, const int* in_sizes, int n_in,
                              void* d_out, int out_size) {
    const float* features = (const float*)d_in[0];
    int n  = in_sizes[0] / DIM;   // 8192
    int g  = in_sizes[1];         // 2048
    int cr = n / g;               // 4

    const int SMEM_DYN = 32768;   // B panel only
    cudaFuncSetAttribute(k_scores_sym,
                         cudaFuncAttributeMaxDynamicSharedMemorySize, SMEM_DYN);

    k_normalize<<<n / 8, 256>>>(features, n);
    k_scores_sym<<<NTRI, 256, SMEM_DYN>>>();
    k_rowloss<<<n / 8, 256>>>((float*)d_out, n, cr);
}

// round 9
// speedup vs baseline: 1.5890x; 1.5230x over previous
#include <cuda_runtime.h>
#include <cuda_bf16.h>
#include <math.h>
#include <stdint.h>

// Problem constants (reference: G=2048, CROPS=4, D=128 -> N=8192)
#define N_ROWS 8192
#define DIM    128
#define NP     (N_ROWS / 128)            // 64 row panels

#define EXP2_SCALE 2.8853900817779268f   // 1/(tau*ln2), tau=0.5
#define SQRT_E2S   1.6986436f            // sqrt(EXP2_SCALE), folded into bf16 z
#define EXP_SELF   7.38905609893065f     // exp(1/tau) = e^2

// Scratch (device globals; no allocation anywhere)
__device__ float          g_z[N_ROWS * DIM];        // fp32 normalized (unscaled)
__device__ __nv_bfloat16  g_zb[N_ROWS * DIM];       // bf16 normalized * sqrt(scale)
__device__ float          g_P[N_ROWS * NP];         // [row][slot] partial sums (slot-contiguous)
__device__ float          g_part[N_ROWS / 8];       // per-CTA partial losses
__device__ int            g_sync;                   // last-CTA counter (self-resetting)

// ---------------------------------------------------------------------------
// helpers
// ---------------------------------------------------------------------------
static __device__ __forceinline__ uint32_t smem_u32(const void* p) {
    uint32_t a;
    asm("{ .reg .u64 t; cvta.to.shared.u64 t, %1; cvt.u32.u64 %0, t; }"
        : "=r"(a) : "l"(p));
    return a;
}

#define LDSM_X4(r0, r1, r2, r3, addr)                                          \
    asm volatile("ldmatrix.sync.aligned.m8n8.x4.shared.b16 {%0,%1,%2,%3}, [%4];" \
                 : "=r"(r0), "=r"(r1), "=r"(r2), "=r"(r3) : "r"(addr))

#define MMA16816(d, a, b0, b1)                                                 \
    asm volatile("mma.sync.aligned.m16n8k16.row.col.f32.bf16.bf16.f32 "        \
                 "{%0,%1,%2,%3},{%4,%5,%6,%7},{%8,%9},{%0,%1,%2,%3};"          \
                 : "+f"((d)[0]), "+f"((d)[1]), "+f"((d)[2]), "+f"((d)[3])      \
                 : "r"((a)[0]), "r"((a)[1]), "r"((a)[2]), "r"((a)[3]),         \
                   "r"(b0), "r"(b1))

#define CP_ASYNC16(dst, src)                                                   \
    asm volatile("cp.async.cg.shared.global [%0], [%1], 16;"                   \
                 :: "r"(dst), "l"(src) : "memory")
#define CP_COMMIT() asm volatile("cp.async.commit_group;" ::: "memory")
#define CP_WAIT(N)  asm volatile("cp.async.wait_group %0;" :: "n"(N) : "memory")

static __device__ __forceinline__ float ex2_fast(float x) {
    float y;
    asm("ex2.approx.ftz.f32 %0, %1;" : "=f"(y) : "f"(x));
    return y;
}

// Swizzled tile layout (128 rows x 16 chunks of 16B, conflict-free ldmatrix):
// off(r,c) = (c>>3)*16384 + r*128 + ((c&7)^(r&7))*16
static __device__ __forceinline__ uint32_t tile_off(int r, int c) {
    return ((uint32_t)(c >> 3) << 14) + ((uint32_t)r << 7)
         + ((uint32_t)((c & 7) ^ (r & 7)) << 4);
}

// async-copy one 128x128 bf16 panel (rows r0..r0+127) into swizzled smem
static __device__ __forceinline__ void cp_tile(uint32_t dst, int r0, int tid) {
    const char* src = (const char*)g_zb + (size_t)r0 * 256;
    #pragma unroll
    for (int it = 0; it < 8; it++) {
        int idx = tid + it * 256;       // 2048 chunks of 16B
        int r = idx >> 4;
        int c = idx & 15;
        CP_ASYNC16(dst + tile_off(r, c), src + (size_t)r * 256 + c * 16);
    }
}

// ---------------------------------------------------------------------------
// Kernel A: row-normalize (float4-vectorized); fp32 copy + bf16*sqrt(scale)
// ---------------------------------------------------------------------------
__global__ void k_normalize(const float* __restrict__ f, int n) {
    int warp = (blockIdx.x * blockDim.x + threadIdx.x) >> 5;
    int lane = threadIdx.x & 31;
    if (warp >= n) return;
    const float4* row = (const float4*)(f + (size_t)warp * DIM);
    float4 v = row[lane];
    float ss = v.x * v.x + v.y * v.y + v.z * v.z + v.w * v.w;
    #pragma unroll
    for (int o = 16; o; o >>= 1) ss += __shfl_xor_sync(0xffffffffu, ss, o);
    float inv = 1.0f / fmaxf(sqrtf(ss), 1e-8f);
    float4 z;
    z.x = v.x * inv; z.y = v.y * inv; z.z = v.z * inv; z.w = v.w * inv;
    ((float4*)(g_z + (size_t)warp * DIM))[lane] = z;

    __nv_bfloat162 lo = __floats2bfloat162_rn(z.x * SQRT_E2S, z.y * SQRT_E2S);
    __nv_bfloat162 hi = __floats2bfloat162_rn(z.z * SQRT_E2S, z.w * SQRT_E2S);
    uint2 pk;
    pk.x = *(uint32_t*)&lo;
    pk.y = *(uint32_t*)&hi;
    ((uint2*)(g_zb + (size_t)warp * DIM))[lane] = pk;
}

// ---------------------------------------------------------------------------
// Kernel B: symmetric-tile HMMA, one 128x128 tile per CTA, occupancy 3.
// (round-6 winning body, unchanged except g_P store layout)
// ---------------------------------------------------------------------------
__global__ void __launch_bounds__(256, 3)
k_scores_sym() {
    const int I = blockIdx.x;
    const int J = blockIdx.y;
    if (J < I) return;

    extern __shared__ __align__(1024) char smem[];
    __shared__ float red[128][2];      // row sums: [row][warpN]
    __shared__ float colred[128][4];   // col sums: [col][warpM]

    const uint32_t Abase = smem_u32(smem);
    const uint32_t Bbase = Abase + 32768;

    const int tid   = threadIdx.x;
    const int lane  = tid & 31;
    const int w     = tid >> 5;
    const int warpM = w & 3;
    const int warpN = w >> 2;

    cp_tile(Abase, I * 128, tid);
    cp_tile(Bbase, J * 128, tid);
    CP_COMMIT();
    CP_WAIT(0);
    __syncthreads();

    const int aRow = warpM * 32 + (lane & 15);
    const int aSel = lane >> 4;
    const int bRow = (lane & 7) + ((lane >> 4) & 1) * 8;
    const int bSel = (lane >> 3) & 1;

    float rs[2][2] = {{0.f, 0.f}, {0.f, 0.f}};

    #pragma unroll
    for (int nbb = 0; nbb < 2; nbb++) {       // n-half-block: cols nbb*32..+31
        float acc[2][2][2][4];                 // [mb][nb2loc][sub][q]
        #pragma unroll
        for (int mb = 0; mb < 2; mb++)
            #pragma unroll
            for (int u = 0; u < 2; u++)
                #pragma unroll
                for (int v = 0; v < 2; v++)
                    #pragma unroll
                    for (int q = 0; q < 4; q++) acc[mb][u][v][q] = 0.0f;

        #pragma unroll
        for (int ks = 0; ks < 8; ks++) {
            uint32_t af[2][4];
            #pragma unroll
            for (int mb = 0; mb < 2; mb++)
                LDSM_X4(af[mb][0], af[mb][1], af[mb][2], af[mb][3],
                        Abase + tile_off(aRow + mb * 16, ks * 2 + aSel));
            #pragma unroll
            for (int u = 0; u < 2; u++) {
                uint32_t b0, b1, b2, b3;
                LDSM_X4(b0, b1, b2, b3,
                        Bbase + tile_off(warpN * 64 + (nbb * 2 + u) * 16 + bRow,
                                         ks * 2 + bSel));
                #pragma unroll
                for (int mb = 0; mb < 2; mb++) {
                    MMA16816(acc[mb][u][0], af[mb], b0, b1);
                    MMA16816(acc[mb][u][1], af[mb], b2, b3);
                }
            }
        }

        // Block epilogue: ex2 + row/col partial sums (overlaps next block's MMAs)
        float cs[8];
        #pragma unroll
        for (int k = 0; k < 8; k++) cs[k] = 0.f;

        #pragma unroll
        for (int mb = 0; mb < 2; mb++)
            #pragma unroll
            for (int u = 0; u < 2; u++)
                #pragma unroll
                for (int v = 0; v < 2; v++)
                    #pragma unroll
                    for (int q = 0; q < 4; q++) {
                        float e = ex2_fast(acc[mb][u][v][q]);
                        rs[mb][q >> 1]                += e;
                        cs[(u * 2 + v) * 2 + (q & 1)] += e;
                    }

        // col reduce across lane>>2 (rows); lane<4 then holds col groups
        #pragma unroll
        for (int k = 0; k < 8; k++) {
            cs[k] += __shfl_xor_sync(0xffffffffu, cs[k], 4);
            cs[k] += __shfl_xor_sync(0xffffffffu, cs[k], 8);
            cs[k] += __shfl_xor_sync(0xffffffffu, cs[k], 16);
        }
        if (lane < 4) {
            #pragma unroll
            for (int k = 0; k < 8; k++) {
                int nb = nbb * 4 + (k >> 1);           // global 8-col group
                colred[warpN * 64 + nb * 8 + lane * 2 + (k & 1)][warpM] = cs[k];
            }
        }
    }

    // row reduce across lane&3 (cols)
    #pragma unroll
    for (int mb = 0; mb < 2; mb++)
        #pragma unroll
        for (int h = 0; h < 2; h++) {
            rs[mb][h] += __shfl_xor_sync(0xffffffffu, rs[mb][h], 1);
            rs[mb][h] += __shfl_xor_sync(0xffffffffu, rs[mb][h], 2);
        }
    if ((lane & 3) == 0) {
        int gq = lane >> 2;
        #pragma unroll
        for (int mb = 0; mb < 2; mb++)
            #pragma unroll
            for (int h = 0; h < 2; h++)
                red[warpM * 32 + mb * 16 + h * 8 + gq][warpN] = rs[mb][h];
    }
    __syncthreads();

    // store: slot-contiguous layout g_P[row * NP + slot]
    if (tid < 128) {
        float r = red[tid][0] + red[tid][1];
        g_P[(size_t)(I * 128 + tid) * NP + J] = r;
        if (I != J) {
            float c = colred[tid][0] + colred[tid][1]
                    + colred[tid][2] + colred[tid][3];
            g_P[(size_t)(J * 128 + tid) * NP + I] = c;
        }
    }
}

// ---------------------------------------------------------------------------
// Kernel C: coalesced S gather + fp32 pos + per-row loss + CTA partials +
// fused final reduction (deterministic last-CTA pattern; self-resetting)
// ---------------------------------------------------------------------------
__global__ void k_rowloss(float* __restrict__ out, int n, int cr) {
    __shared__ float tvals[8];
    __shared__ int   s_last;
    __shared__ float sm[256];

    int row  = blockIdx.x * 8 + (threadIdx.x >> 5);
    int lane = threadIdx.x & 31;
    float tv = 0.0f;
    if (row < n) {
        const float* zr = g_z + (size_t)row * DIM;
        float a0 = zr[lane], a1 = zr[lane + 32], a2 = zr[lane + 64], a3 = zr[lane + 96];
        int gb = (row / cr) * cr;
        float P = 0.0f;
        for (int jj = 0; jj < cr; jj++) {
            const float* zc = g_z + (size_t)(gb + jj) * DIM;
            float d = a0 * zc[lane] + a1 * zc[lane + 32] + a2 * zc[lane + 64] + a3 * zc[lane + 96];
            #pragma unroll
            for (int o = 16; o; o >>= 1) d += __shfl_xor_sync(0xffffffffu, d, o);
            P += exp2f(d * EXP2_SCALE);
        }
        // coalesced gather: slots contiguous per row
        const float* pbase = g_P + (size_t)row * NP;
        float s = pbase[lane] + pbase[lane + 32];
        #pragma unroll
        for (int o = 16; o; o >>= 1) s += __shfl_xor_sync(0xffffffffu, s, o);

        float pos = P - EXP_SELF;
        float neg = s - P;
        tv = logf(neg) - logf(pos);
    }
    if (lane == 0) tvals[threadIdx.x >> 5] = tv;
    __syncthreads();
    if (threadIdx.x == 0) {
        float acc = 0.0f;
        #pragma unroll
        for (int u = 0; u < 8; u++) acc += tvals[u];
        g_part[blockIdx.x] = acc;
        __threadfence();
        int old = atomicAdd(&g_sync, 1);
        s_last = (old == (int)gridDim.x - 1);
    }
    __syncthreads();

    if (s_last) {
        if (threadIdx.x == 0) g_sync = 0;   // reset for next graph replay
        __threadfence();
        int t = threadIdx.x;
        int m = gridDim.x;
        float s = 0.0f;
        for (int idx = t; idx < m; idx += 256)
            s += __ldcg(&g_part[idx]);      // fixed-order, L2 loads
        sm[t] = s;
        __syncthreads();
        #pragma unroll
        for (int off = 128; off; off >>= 1) {
            if (t < off) sm[t] += sm[t + off];
            __syncthreads();
        }
        if (t == 0) out[0] = sm[0] / (float)n;
    }
}

// ---------------------------------------------------------------------------
extern "C" void kernel_launch(void* const* d_in, const int* in_sizes, int n_in,
                              void* d_out, int out_size) {
    const float* features = (const float*)d_in[0];
    int n  = in_sizes[0] / DIM;   // 8192
    int g  = in_sizes[1];         // 2048
    int cr = n / g;               // 4

    const int SMEM_DYN = 2 * 32768;   // A panel + B panel
    cudaFuncSetAttribute(k_scores_sym,
                         cudaFuncAttributeMaxDynamicSharedMemorySize, SMEM_DYN);

    k_normalize<<<n / 8, 256>>>(features, n);
    dim3 grid_b(NP, NP);
    k_scores_sym<<<grid_b, 256, SMEM_DYN>>>();
    k_rowloss<<<n / 8, 256>>>((float*)d_out, n, cr);
}

// round 10
// speedup vs baseline: 1.5902x; 1.0008x over previous
#include <cuda_runtime.h>
#include <cuda_bf16.h>
#include <math.h>
#include <stdint.h>

// Problem constants (reference: G=2048, CROPS=4, D=128 -> N=8192)
#define N_ROWS 8192
#define DIM    128
#define NP     (N_ROWS / 128)            // 64 row panels

#define EXP2_SCALE 2.8853900817779268f   // 1/(tau*ln2), tau=0.5
#define SQRT_E2S   1.6986436f            // sqrt(EXP2_SCALE), folded into bf16 z
#define EXP_SELF   7.38905609893065f     // exp(1/tau) = e^2

// Scratch (device globals; no allocation anywhere)
__device__ __nv_bfloat16  g_zb[N_ROWS * DIM];       // bf16 normalized * sqrt(scale)
__device__ float          g_P[NP * NP * 128];       // [I][J][row] partial sums
__device__ float          g_part[NP];               // per-panel partial losses
__device__ int            g_sync;                   // last-CTA counter (self-resetting)

// ---------------------------------------------------------------------------
// helpers
// ---------------------------------------------------------------------------
static __device__ __forceinline__ uint32_t smem_u32(const void* p) {
    uint32_t a;
    asm("{ .reg .u64 t; cvta.to.shared.u64 t, %1; cvt.u32.u64 %0, t; }"
        : "=r"(a) : "l"(p));
    return a;
}

#define LDSM_X4(r0, r1, r2, r3, addr)                                          \
    asm volatile("ldmatrix.sync.aligned.m8n8.x4.shared.b16 {%0,%1,%2,%3}, [%4];" \
                 : "=r"(r0), "=r"(r1), "=r"(r2), "=r"(r3) : "r"(addr))

#define MMA16816(d, a, b0, b1)                                                 \
    asm volatile("mma.sync.aligned.m16n8k16.row.col.f32.bf16.bf16.f32 "        \
                 "{%0,%1,%2,%3},{%4,%5,%6,%7},{%8,%9},{%0,%1,%2,%3};"          \
                 : "+f"((d)[0]), "+f"((d)[1]), "+f"((d)[2]), "+f"((d)[3])      \
                 : "r"((a)[0]), "r"((a)[1]), "r"((a)[2]), "r"((a)[3]),         \
                   "r"(b0), "r"(b1))

#define CP_ASYNC16(dst, src)                                                   \
    asm volatile("cp.async.cg.shared.global [%0], [%1], 16;"                   \
                 :: "r"(dst), "l"(src) : "memory")
#define CP_COMMIT() asm volatile("cp.async.commit_group;" ::: "memory")
#define CP_WAIT(N)  asm volatile("cp.async.wait_group %0;" :: "n"(N) : "memory")

static __device__ __forceinline__ float ex2_fast(float x) {
    float y;
    asm("ex2.approx.ftz.f32 %0, %1;" : "=f"(y) : "f"(x));
    return y;
}

// Swizzled tile layout (128 rows x 16 chunks of 16B, conflict-free ldmatrix):
// off(r,c) = (c>>3)*16384 + r*128 + ((c&7)^(r&7))*16
static __device__ __forceinline__ uint32_t tile_off(int r, int c) {
    return ((uint32_t)(c >> 3) << 14) + ((uint32_t)r << 7)
         + ((uint32_t)((c & 7) ^ (r & 7)) << 4);
}

// async-copy one 128x128 bf16 panel (rows r0..r0+127) into swizzled smem
static __device__ __forceinline__ void cp_tile(uint32_t dst, int r0, int tid) {
    const char* src = (const char*)g_zb + (size_t)r0 * 256;
    #pragma unroll
    for (int it = 0; it < 8; it++) {
        int idx = tid + it * 256;       // 2048 chunks of 16B
        int r = idx >> 4;
        int c = idx & 15;
        CP_ASYNC16(dst + tile_off(r, c), src + (size_t)r * 256 + c * 16);
    }
}

// ---------------------------------------------------------------------------
// Kernel A: row-normalize (float4); write ONLY bf16 * sqrt(EXP2_SCALE)
// ---------------------------------------------------------------------------
__global__ void k_normalize(const float* __restrict__ f, int n) {
    int warp = (blockIdx.x * blockDim.x + threadIdx.x) >> 5;
    int lane = threadIdx.x & 31;
    if (warp >= n) return;
    const float4* row = (const float4*)(f + (size_t)warp * DIM);
    float4 v = row[lane];
    float ss = v.x * v.x + v.y * v.y + v.z * v.z + v.w * v.w;
    #pragma unroll
    for (int o = 16; o; o >>= 1) ss += __shfl_xor_sync(0xffffffffu, ss, o);
    float inv = SQRT_E2S / fmaxf(sqrtf(ss), 1e-8f);
    __nv_bfloat162 lo = __floats2bfloat162_rn(v.x * inv, v.y * inv);
    __nv_bfloat162 hi = __floats2bfloat162_rn(v.z * inv, v.w * inv);
    uint2 pk;
    pk.x = *(uint32_t*)&lo;
    pk.y = *(uint32_t*)&hi;
    ((uint2*)(g_zb + (size_t)warp * DIM))[lane] = pk;
}

// ---------------------------------------------------------------------------
// Kernel B: symmetric-tile HMMA, one 128x128 tile per CTA, occupancy 3.
// (round-6 winning body, unchanged)
// ---------------------------------------------------------------------------
__global__ void __launch_bounds__(256, 3)
k_scores_sym() {
    const int I = blockIdx.x;
    const int J = blockIdx.y;
    if (J < I) return;

    extern __shared__ __align__(1024) char smem[];
    __shared__ float red[128][2];      // row sums: [row][warpN]
    __shared__ float colred[128][4];   // col sums: [col][warpM]

    const uint32_t Abase = smem_u32(smem);
    const uint32_t Bbase = Abase + 32768;

    const int tid   = threadIdx.x;
    const int lane  = tid & 31;
    const int w     = tid >> 5;
    const int warpM = w & 3;
    const int warpN = w >> 2;

    cp_tile(Abase, I * 128, tid);
    cp_tile(Bbase, J * 128, tid);
    CP_COMMIT();
    CP_WAIT(0);
    __syncthreads();

    const int aRow = warpM * 32 + (lane & 15);
    const int aSel = lane >> 4;
    const int bRow = (lane & 7) + ((lane >> 4) & 1) * 8;
    const int bSel = (lane >> 3) & 1;

    float rs[2][2] = {{0.f, 0.f}, {0.f, 0.f}};

    #pragma unroll
    for (int nbb = 0; nbb < 2; nbb++) {       // n-half-block: cols nbb*32..+31
        float acc[2][2][2][4];                 // [mb][nb2loc][sub][q]
        #pragma unroll
        for (int mb = 0; mb < 2; mb++)
            #pragma unroll
            for (int u = 0; u < 2; u++)
                #pragma unroll
                for (int v = 0; v < 2; v++)
                    #pragma unroll
                    for (int q = 0; q < 4; q++) acc[mb][u][v][q] = 0.0f;

        #pragma unroll
        for (int ks = 0; ks < 8; ks++) {
            uint32_t af[2][4];
            #pragma unroll
            for (int mb = 0; mb < 2; mb++)
                LDSM_X4(af[mb][0], af[mb][1], af[mb][2], af[mb][3],
                        Abase + tile_off(aRow + mb * 16, ks * 2 + aSel));
            #pragma unroll
            for (int u = 0; u < 2; u++) {
                uint32_t b0, b1, b2, b3;
                LDSM_X4(b0, b1, b2, b3,
                        Bbase + tile_off(warpN * 64 + (nbb * 2 + u) * 16 + bRow,
                                         ks * 2 + bSel));
                #pragma unroll
                for (int mb = 0; mb < 2; mb++) {
                    MMA16816(acc[mb][u][0], af[mb], b0, b1);
                    MMA16816(acc[mb][u][1], af[mb], b2, b3);
                }
            }
        }

        // Block epilogue: ex2 + row/col partial sums (overlaps next block's MMAs)
        float cs[8];
        #pragma unroll
        for (int k = 0; k < 8; k++) cs[k] = 0.f;

        #pragma unroll
        for (int mb = 0; mb < 2; mb++)
            #pragma unroll
            for (int u = 0; u < 2; u++)
                #pragma unroll
                for (int v = 0; v < 2; v++)
                    #pragma unroll
                    for (int q = 0; q < 4; q++) {
                        float e = ex2_fast(acc[mb][u][v][q]);
                        rs[mb][q >> 1]                += e;
                        cs[(u * 2 + v) * 2 + (q & 1)] += e;
                    }

        // col reduce across lane>>2 (rows); lane<4 then holds col groups
        #pragma unroll
        for (int k = 0; k < 8; k++) {
            cs[k] += __shfl_xor_sync(0xffffffffu, cs[k], 4);
            cs[k] += __shfl_xor_sync(0xffffffffu, cs[k], 8);
            cs[k] += __shfl_xor_sync(0xffffffffu, cs[k], 16);
        }
        if (lane < 4) {
            #pragma unroll
            for (int k = 0; k < 8; k++) {
                int nb = nbb * 4 + (k >> 1);           // global 8-col group
                colred[warpN * 64 + nb * 8 + lane * 2 + (k & 1)][warpM] = cs[k];
            }
        }
    }

    // row reduce across lane&3 (cols)
    #pragma unroll
    for (int mb = 0; mb < 2; mb++)
        #pragma unroll
        for (int h = 0; h < 2; h++) {
            rs[mb][h] += __shfl_xor_sync(0xffffffffu, rs[mb][h], 1);
            rs[mb][h] += __shfl_xor_sync(0xffffffffu, rs[mb][h], 2);
        }
    if ((lane & 3) == 0) {
        int gq = lane >> 2;
        #pragma unroll
        for (int mb = 0; mb < 2; mb++)
            #pragma unroll
            for (int h = 0; h < 2; h++)
                red[warpM * 32 + mb * 16 + h * 8 + gq][warpN] = rs[mb][h];
    }
    __syncthreads();

    if (tid < 128) {
        float r = red[tid][0] + red[tid][1];
        g_P[((size_t)I * NP + J) * 128 + tid] = r;
        if (I != J) {
            float c = colred[tid][0] + colred[tid][1]
                    + colred[tid][2] + colred[tid][3];
            g_P[((size_t)J * NP + I) * 128 + tid] = c;
        }
    }
}

// ---------------------------------------------------------------------------
// Kernel C: panel-per-block loss. 64 blocks x 256 threads.
// - bf16 panel staged in smem (32KB), coalesced.
// - S gather coalesced: thread (r, half) sums 32 J-slots at g_P[Ip][J][r].
// - pos from bf16 dots in smem (4-way interleaved shuffle reductions).
// - fused deterministic last-CTA final reduction.
// ---------------------------------------------------------------------------
__global__ void __launch_bounds__(256) k_rowloss(float* __restrict__ out, int n) {
    __shared__ __nv_bfloat16 zb[128 * DIM];   // 32KB panel
    __shared__ float Ssum[128];
    __shared__ float tvals[8];
    __shared__ float sm[256];
    __shared__ int   s_last;

    const int tid  = threadIdx.x;
    const int lane = tid & 31;
    const int wrp  = tid >> 5;
    const int Ip   = blockIdx.x;

    // stage panel (coalesced 16B chunks)
    {
        const uint4* src = (const uint4*)(g_zb + (size_t)Ip * 128 * DIM);
        uint4* dst = (uint4*)zb;
        #pragma unroll
        for (int i = 0; i < 8; i++) dst[tid + i * 256] = src[tid + i * 256];
    }

    // S gather: thread (r = tid&127, half = tid>>7) sums its 32 slots
    {
        int r = tid & 127;
        int half = tid >> 7;
        const float* p = g_P + ((size_t)Ip * NP + half * 32) * 128 + r;
        float s = 0.0f;
        #pragma unroll
        for (int Jl = 0; Jl < 32; Jl++) s += p[(size_t)Jl * 128];
        if (half == 0) Ssum[r] = s;
        __syncthreads();
        if (half == 1) Ssum[r] += s;
    }
    __syncthreads();   // panel + Ssum complete

    // per-row loss: warp handles 16 rows; 4 group-dots interleaved
    float tv = 0.0f;
    for (int rr = 0; rr < 16; rr++) {
        const int r  = wrp * 16 + rr;
        const int gb = r & ~3;              // crops = 4, group-aligned

        const uint2* ar = (const uint2*)(zb + r * DIM) + lane;
        uint2 pa = *ar;
        float2 a01 = __bfloat1622float2(*(const __nv_bfloat162*)&pa.x);
        float2 a23 = __bfloat1622float2(*(const __nv_bfloat162*)&pa.y);

        float d[4];
        #pragma unroll
        for (int c = 0; c < 4; c++) {
            const uint2* br = (const uint2*)(zb + (gb + c) * DIM) + lane;
            uint2 pb = *br;
            float2 b01 = __bfloat1622float2(*(const __nv_bfloat162*)&pb.x);
            float2 b23 = __bfloat1622float2(*(const __nv_bfloat162*)&pb.y);
            d[c] = a01.x * b01.x + a01.y * b01.y + a23.x * b23.x + a23.y * b23.y;
        }
        #pragma unroll
        for (int o = 16; o; o >>= 1) {
            #pragma unroll
            for (int c = 0; c < 4; c++)
                d[c] += __shfl_xor_sync(0xffffffffu, d[c], o);
        }
        // zb is pre-scaled: d = cos/(tau*ln2) already
        float P = ex2_fast(d[0]) + ex2_fast(d[1]) + ex2_fast(d[2]) + ex2_fast(d[3]);
        float S = Ssum[r];
        float pos = P - EXP_SELF;
        float neg = S - P;
        if (lane == 0) tv += logf(neg) - logf(pos);
    }

    if (lane == 0) tvals[wrp] = tv;
    __syncthreads();
    if (tid == 0) {
        float acc = 0.0f;
        #pragma unroll
        for (int u = 0; u < 8; u++) acc += tvals[u];
        g_part[Ip] = acc;
        __threadfence();
        int old = atomicAdd(&g_sync, 1);
        s_last = (old == (int)gridDim.x - 1);
    }
    __syncthreads();

    if (s_last) {
        if (tid == 0) g_sync = 0;   // reset for next graph replay
        __threadfence();
        int m = gridDim.x;
        float s = 0.0f;
        for (int idx = tid; idx < m; idx += 256)
            s += __ldcg(&g_part[idx]);
        sm[tid] = s;
        __syncthreads();
        #pragma unroll
        for (int off = 128; off; off >>= 1) {
            if (tid < off) sm[tid] += sm[tid + off];
            __syncthreads();
        }
        if (tid == 0) out[0] = sm[0] / (float)n;
    }
}

// ---------------------------------------------------------------------------
extern "C" void kernel_launch(void* const* d_in, const int* in_sizes, int n_in,
                              void* d_out, int out_size) {
    const float* features = (const float*)d_in[0];
    int n = in_sizes[0] / DIM;   // 8192

    const int SMEM_DYN = 2 * 32768;   // A panel + B panel
    cudaFuncSetAttribute(k_scores_sym,
                         cudaFuncAttributeMaxDynamicSharedMemorySize, SMEM_DYN);

    k_normalize<<<n / 8, 256>>>(features, n);
    dim3 grid_b(NP, NP);
    k_scores_sym<<<grid_b, 256, SMEM_DYN>>>();
    k_rowloss<<<NP, 256>>>((float*)d_out, n);
}

// round 11
// speedup vs baseline: 1.7755x; 1.1165x over previous
#include <cuda_runtime.h>
#include <cuda_bf16.h>
#include <math.h>
#include <stdint.h>

// Problem constants (reference: G=2048, CROPS=4, D=128 -> N=8192)
#define N_ROWS 8192
#define DIM    128
#define NP     (N_ROWS / 128)            // 64 row panels

#define EXP2_SCALE 2.8853900817779268f   // 1/(tau*ln2), tau=0.5
#define SQRT_E2S   1.6986436f            // sqrt(EXP2_SCALE), folded into bf16 z
#define EXP_SELF   7.38905609893065f     // exp(1/tau) = e^2

// Scratch (device globals; no allocation anywhere)
__device__ __nv_bfloat16  g_zb[N_ROWS * DIM];       // bf16 normalized * sqrt(scale)
__device__ float          g_P[NP * NP * 128];       // [I][J][row] partial sums
__device__ float          g_part[N_ROWS / 32];      // per-block partial losses (256)
__device__ int            g_sync;                   // last-CTA counter (self-resetting)

// ---------------------------------------------------------------------------
// helpers
// ---------------------------------------------------------------------------
static __device__ __forceinline__ uint32_t smem_u32(const void* p) {
    uint32_t a;
    asm("{ .reg .u64 t; cvta.to.shared.u64 t, %1; cvt.u32.u64 %0, t; }"
        : "=r"(a) : "l"(p));
    return a;
}

#define LDSM_X4(r0, r1, r2, r3, addr)                                          \
    asm volatile("ldmatrix.sync.aligned.m8n8.x4.shared.b16 {%0,%1,%2,%3}, [%4];" \
                 : "=r"(r0), "=r"(r1), "=r"(r2), "=r"(r3) : "r"(addr))

#define MMA16816(d, a, b0, b1)                                                 \
    asm volatile("mma.sync.aligned.m16n8k16.row.col.f32.bf16.bf16.f32 "        \
                 "{%0,%1,%2,%3},{%4,%5,%6,%7},{%8,%9},{%0,%1,%2,%3};"          \
                 : "+f"((d)[0]), "+f"((d)[1]), "+f"((d)[2]), "+f"((d)[3])      \
                 : "r"((a)[0]), "r"((a)[1]), "r"((a)[2]), "r"((a)[3]),         \
                   "r"(b0), "r"(b1))

#define CP_ASYNC16(dst, src)                                                   \
    asm volatile("cp.async.cg.shared.global [%0], [%1], 16;"                   \
                 :: "r"(dst), "l"(src) : "memory")
#define CP_COMMIT() asm volatile("cp.async.commit_group;" ::: "memory")
#define CP_WAIT(N)  asm volatile("cp.async.wait_group %0;" :: "n"(N) : "memory")

static __device__ __forceinline__ float ex2_fast(float x) {
    float y;
    asm("ex2.approx.ftz.f32 %0, %1;" : "=f"(y) : "f"(x));
    return y;
}

// Swizzled tile layout (128 rows x 16 chunks of 16B, conflict-free ldmatrix):
// off(r,c) = (c>>3)*16384 + r*128 + ((c&7)^(r&7))*16
static __device__ __forceinline__ uint32_t tile_off(int r, int c) {
    return ((uint32_t)(c >> 3) << 14) + ((uint32_t)r << 7)
         + ((uint32_t)((c & 7) ^ (r & 7)) << 4);
}

// async-copy one 128x128 bf16 panel (rows r0..r0+127) into swizzled smem
static __device__ __forceinline__ void cp_tile(uint32_t dst, int r0, int tid) {
    const char* src = (const char*)g_zb + (size_t)r0 * 256;
    #pragma unroll
    for (int it = 0; it < 8; it++) {
        int idx = tid + it * 256;       // 2048 chunks of 16B
        int r = idx >> 4;
        int c = idx & 15;
        CP_ASYNC16(dst + tile_off(r, c), src + (size_t)r * 256 + c * 16);
    }
}

// ---------------------------------------------------------------------------
// Kernel A: row-normalize, 4 rows per warp (MLP=4); bf16 * sqrt(EXP2_SCALE)
// ---------------------------------------------------------------------------
__global__ void k_normalize(const float* __restrict__ f, int n) {
    int wid  = (blockIdx.x * blockDim.x + threadIdx.x) >> 5;
    int lane = threadIdx.x & 31;
    int r0 = wid * 4;
    if (r0 >= n) return;

    float4 v[4];
    float  ss[4];
    #pragma unroll
    for (int i = 0; i < 4; i++) {
        v[i] = ((const float4*)(f + (size_t)(r0 + i) * DIM))[lane];
        ss[i] = v[i].x * v[i].x + v[i].y * v[i].y
              + v[i].z * v[i].z + v[i].w * v[i].w;
    }
    #pragma unroll
    for (int o = 16; o; o >>= 1) {
        #pragma unroll
        for (int i = 0; i < 4; i++)
            ss[i] += __shfl_xor_sync(0xffffffffu, ss[i], o);
    }
    #pragma unroll
    for (int i = 0; i < 4; i++) {
        float inv = SQRT_E2S / fmaxf(sqrtf(ss[i]), 1e-8f);
        __nv_bfloat162 lo = __floats2bfloat162_rn(v[i].x * inv, v[i].y * inv);
        __nv_bfloat162 hi = __floats2bfloat162_rn(v[i].z * inv, v[i].w * inv);
        uint2 pk;
        pk.x = *(uint32_t*)&lo;
        pk.y = *(uint32_t*)&hi;
        ((uint2*)(g_zb + (size_t)(r0 + i) * DIM))[lane] = pk;
    }
}

// ---------------------------------------------------------------------------
// Kernel B: symmetric-tile HMMA, one 128x128 tile per CTA, occupancy 3.
// (round-6 winning body, unchanged)
// ---------------------------------------------------------------------------
__global__ void __launch_bounds__(256, 3)
k_scores_sym() {
    const int I = blockIdx.x;
    const int J = blockIdx.y;
    if (J < I) return;

    extern __shared__ __align__(1024) char smem[];
    __shared__ float red[128][2];      // row sums: [row][warpN]
    __shared__ float colred[128][4];   // col sums: [col][warpM]

    const uint32_t Abase = smem_u32(smem);
    const uint32_t Bbase = Abase + 32768;

    const int tid   = threadIdx.x;
    const int lane  = tid & 31;
    const int w     = tid >> 5;
    const int warpM = w & 3;
    const int warpN = w >> 2;

    cp_tile(Abase, I * 128, tid);
    cp_tile(Bbase, J * 128, tid);
    CP_COMMIT();
    CP_WAIT(0);
    __syncthreads();

    const int aRow = warpM * 32 + (lane & 15);
    const int aSel = lane >> 4;
    const int bRow = (lane & 7) + ((lane >> 4) & 1) * 8;
    const int bSel = (lane >> 3) & 1;

    float rs[2][2] = {{0.f, 0.f}, {0.f, 0.f}};

    #pragma unroll
    for (int nbb = 0; nbb < 2; nbb++) {       // n-half-block: cols nbb*32..+31
        float acc[2][2][2][4];                 // [mb][nb2loc][sub][q]
        #pragma unroll
        for (int mb = 0; mb < 2; mb++)
            #pragma unroll
            for (int u = 0; u < 2; u++)
                #pragma unroll
                for (int v = 0; v < 2; v++)
                    #pragma unroll
                    for (int q = 0; q < 4; q++) acc[mb][u][v][q] = 0.0f;

        #pragma unroll
        for (int ks = 0; ks < 8; ks++) {
            uint32_t af[2][4];
            #pragma unroll
            for (int mb = 0; mb < 2; mb++)
                LDSM_X4(af[mb][0], af[mb][1], af[mb][2], af[mb][3],
                        Abase + tile_off(aRow + mb * 16, ks * 2 + aSel));
            #pragma unroll
            for (int u = 0; u < 2; u++) {
                uint32_t b0, b1, b2, b3;
                LDSM_X4(b0, b1, b2, b3,
                        Bbase + tile_off(warpN * 64 + (nbb * 2 + u) * 16 + bRow,
                                         ks * 2 + bSel));
                #pragma unroll
                for (int mb = 0; mb < 2; mb++) {
                    MMA16816(acc[mb][u][0], af[mb], b0, b1);
                    MMA16816(acc[mb][u][1], af[mb], b2, b3);
                }
            }
        }

        // Block epilogue: ex2 + row/col partial sums (overlaps next block's MMAs)
        float cs[8];
        #pragma unroll
        for (int k = 0; k < 8; k++) cs[k] = 0.f;

        #pragma unroll
        for (int mb = 0; mb < 2; mb++)
            #pragma unroll
            for (int u = 0; u < 2; u++)
                #pragma unroll
                for (int v = 0; v < 2; v++)
                    #pragma unroll
                    for (int q = 0; q < 4; q++) {
                        float e = ex2_fast(acc[mb][u][v][q]);
                        rs[mb][q >> 1]                += e;
                        cs[(u * 2 + v) * 2 + (q & 1)] += e;
                    }

        // col reduce across lane>>2 (rows); lane<4 then holds col groups
        #pragma unroll
        for (int k = 0; k < 8; k++) {
            cs[k] += __shfl_xor_sync(0xffffffffu, cs[k], 4);
            cs[k] += __shfl_xor_sync(0xffffffffu, cs[k], 8);
            cs[k] += __shfl_xor_sync(0xffffffffu, cs[k], 16);
        }
        if (lane < 4) {
            #pragma unroll
            for (int k = 0; k < 8; k++) {
                int nb = nbb * 4 + (k >> 1);           // global 8-col group
                colred[warpN * 64 + nb * 8 + lane * 2 + (k & 1)][warpM] = cs[k];
            }
        }
    }

    // row reduce across lane&3 (cols)
    #pragma unroll
    for (int mb = 0; mb < 2; mb++)
        #pragma unroll
        for (int h = 0; h < 2; h++) {
            rs[mb][h] += __shfl_xor_sync(0xffffffffu, rs[mb][h], 1);
            rs[mb][h] += __shfl_xor_sync(0xffffffffu, rs[mb][h], 2);
        }
    if ((lane & 3) == 0) {
        int gq = lane >> 2;
        #pragma unroll
        for (int mb = 0; mb < 2; mb++)
            #pragma unroll
            for (int h = 0; h < 2; h++)
                red[warpM * 32 + mb * 16 + h * 8 + gq][warpN] = rs[mb][h];
    }
    __syncthreads();

    if (tid < 128) {
        float r = red[tid][0] + red[tid][1];
        g_P[((size_t)I * NP + J) * 128 + tid] = r;
        if (I != J) {
            float c = colred[tid][0] + colred[tid][1]
                    + colred[tid][2] + colred[tid][3];
            g_P[((size_t)J * NP + I) * 128 + tid] = c;
        }
    }
}

// ---------------------------------------------------------------------------
// Kernel C: 256 blocks x 32 rows. Warp = one crop-group (4 rows): 4x4 gram
// block via 16 interleaved shuffle chains; rows read coalesced from gmem.
// S gathered coalesced. Fused deterministic last-CTA final reduction.
// ---------------------------------------------------------------------------
__global__ void __launch_bounds__(256) k_rowloss(float* __restrict__ out, int n) {
    __shared__ float Sparts[8][32];   // [part][local row]
    __shared__ float tvals[8];
    __shared__ float sm[256];
    __shared__ int   s_last;

    const int tid  = threadIdx.x;
    const int lane = tid & 31;
    const int wrp  = tid >> 5;
    const int b    = blockIdx.x;          // 32-row block
    const int Ip   = b >> 2;              // panel
    const int rbase = (b & 3) * 32;       // row offset within panel

    // S gather: thread (r = tid&31, part = tid>>5) sums 8 slots, coalesced
    {
        int r = tid & 31;
        int part = tid >> 5;
        const float* p = g_P + ((size_t)Ip * NP + part * 8) * 128 + rbase + r;
        float s = 0.0f;
        #pragma unroll
        for (int j = 0; j < 8; j++) s += p[(size_t)j * 128];
        Sparts[part][r] = s;
    }

    // group gram block: warp wrp owns rows b*32 + wrp*4 .. +3 (one group)
    const int grow = b * 32 + wrp * 4;
    float2 a[4][2];
    #pragma unroll
    for (int i = 0; i < 4; i++) {
        uint2 pk = ((const uint2*)(g_zb + (size_t)(grow + i) * DIM))[lane];
        a[i][0] = __bfloat1622float2(*(const __nv_bfloat162*)&pk.x);
        a[i][1] = __bfloat1622float2(*(const __nv_bfloat162*)&pk.y);
    }

    float d[16];
    #pragma unroll
    for (int i = 0; i < 4; i++)
        #pragma unroll
        for (int j = 0; j < 4; j++)
            d[i * 4 + j] = a[i][0].x * a[j][0].x + a[i][0].y * a[j][0].y
                         + a[i][1].x * a[j][1].x + a[i][1].y * a[j][1].y;

    #pragma unroll
    for (int o = 16; o; o >>= 1) {
        #pragma unroll
        for (int k = 0; k < 16; k++)
            d[k] += __shfl_xor_sync(0xffffffffu, d[k], o);
    }

    __syncthreads();   // Sparts ready

    float tv = 0.0f;
    if (lane < 4) {
        // lane i handles row grow+i (zb pre-scaled: d = cos/(tau*ln2))
        float P = ex2_fast(d[lane * 4 + 0]) + ex2_fast(d[lane * 4 + 1])
                + ex2_fast(d[lane * 4 + 2]) + ex2_fast(d[lane * 4 + 3]);
        int rl = wrp * 4 + lane;
        float S = 0.0f;
        #pragma unroll
        for (int part = 0; part < 8; part++) S += Sparts[part][rl];
        float pos = P - EXP_SELF;
        float neg = S - P;
        tv = logf(neg) - logf(pos);
    }
    tv += __shfl_xor_sync(0xffffffffu, tv, 1);
    tv += __shfl_xor_sync(0xffffffffu, tv, 2);
    if (lane == 0) tvals[wrp] = tv;
    __syncthreads();

    if (tid == 0) {
        float acc = 0.0f;
        #pragma unroll
        for (int u = 0; u < 8; u++) acc += tvals[u];
        g_part[b] = acc;
        __threadfence();
        int old = atomicAdd(&g_sync, 1);
        s_last = (old == (int)gridDim.x - 1);
    }
    __syncthreads();

    if (s_last) {
        if (tid == 0) g_sync = 0;   // reset for next graph replay
        __threadfence();
        int m = gridDim.x;
        float s = 0.0f;
        for (int idx = tid; idx < m; idx += 256)
            s += __ldcg(&g_part[idx]);
        sm[tid] = s;
        __syncthreads();
        #pragma unroll
        for (int off = 128; off; off >>= 1) {
            if (tid < off) sm[tid] += sm[tid + off];
            __syncthreads();
        }
        if (tid == 0) out[0] = sm[0] / (float)n;
    }
}

// ---------------------------------------------------------------------------
extern "C" void kernel_launch(void* const* d_in, const int* in_sizes, int n_in,
                              void* d_out, int out_size) {
    const float* features = (const float*)d_in[0];
    int n = in_sizes[0] / DIM;   // 8192

    const int SMEM_DYN = 2 * 32768;   // A panel + B panel
    cudaFuncSetAttribute(k_scores_sym,
                         cudaFuncAttributeMaxDynamicSharedMemorySize, SMEM_DYN);

    k_normalize<<<n / 32, 256>>>(features, n);
    dim3 grid_b(NP, NP);
    k_scores_sym<<<grid_b, 256, SMEM_DYN>>>();
    k_rowloss<<<n / 32, 256>>>((float*)d_out, n);
}